// round 16
// baseline (speedup 1.0000x reference)
#include <cuda_runtime.h>
#include <cuda_fp16.h>

#define N_USER 100000
#define N_NODES 200000
#define NNZ 6400000
#define EMB 64
#define BATCH 1024

// ---------------- scratch (device globals; no allocation allowed) ----------
__device__ int    g_rowptr[N_NODES + 1];
__device__ __half g_egoh[2][(size_t)N_NODES * EMB];   // fp16 ego ping-pong
__device__ __half g_sideh[(size_t)N_NODES * EMB];
__device__ __half g_prodh[(size_t)N_NODES * EMB];
__device__ __half g_wh[3][128 * EMB];                 // [Wgc;Wbi] fp16, row-major (k,n)
__device__ float  g_bias[3][EMB];                     // bgc + bbi

// ---------------- 1) CSR row_ptr from sorted COO rows ----------------------
__global__ void build_rowptr(const int* __restrict__ row) {
    int r = blockIdx.x * blockDim.x + threadIdx.x;
    if (r > N_NODES) return;
    int lo = 0, hi = NNZ;
    while (lo < hi) {
        int mid = (lo + hi) >> 1;
        if (row[mid] < r) lo = mid + 1; else hi = mid;
    }
    g_rowptr[r] = lo;
}

// ---------------- 2) fp16 ego0 + fp16 weights + fused bias -----------------
__global__ void conv_ego0(const float4* __restrict__ u, const float4* __restrict__ it) {
    int i = blockIdx.x * blockDim.x + threadIdx.x;
    const int NU4 = N_USER * EMB / 4;
    const int NT4 = N_NODES * EMB / 4;
    if (i >= NT4) return;
    float4 v = (i < NU4) ? u[i] : it[i - NU4];
    half2 h0 = __floats2half2_rn(v.x, v.y);
    half2 h1 = __floats2half2_rn(v.z, v.w);
    uint2 pk;
    pk.x = *reinterpret_cast<unsigned*>(&h0);
    pk.y = *reinterpret_cast<unsigned*>(&h1);
    reinterpret_cast<uint2*>(g_egoh[0])[i] = pk;
}

__global__ void conv_weights(const float* Wg0, const float* Wb0, const float* bg0, const float* bb0,
                             const float* Wg1, const float* Wb1, const float* bg1, const float* bb1,
                             const float* Wg2, const float* Wb2, const float* bg2, const float* bb2) {
    const float* Wg[3] = {Wg0, Wg1, Wg2};
    const float* Wb[3] = {Wb0, Wb1, Wb2};
    const float* bg[3] = {bg0, bg1, bg2};
    const float* bb[3] = {bb0, bb1, bb2};
    int i = blockIdx.x * blockDim.x + threadIdx.x;
    if (i < 3 * 128 * EMB) {
        int l = i / (128 * EMB), rem = i % (128 * EMB);
        int k = rem / EMB, n = rem % EMB;
        float w = (k < EMB) ? Wg[l][k * EMB + n] : Wb[l][(k - EMB) * EMB + n];
        g_wh[l][rem] = __float2half_rn(w);
    } else if (i < 3 * 128 * EMB + 3 * EMB) {
        int j = i - 3 * 128 * EMB;
        int l = j / EMB, n = j % EMB;
        g_bias[l][n] = bg[l][n] + bb[l][n];
    }
}

// ---------------- 3) output slice 0 (raw embeddings, gathered) -------------
__global__ void init_out(const int* __restrict__ users, const int* __restrict__ pos,
                         const int* __restrict__ neg,
                         const float* __restrict__ uemb, const float* __restrict__ iemb,
                         float* __restrict__ out) {
    int wid  = (blockIdx.x * blockDim.x + threadIdx.x) >> 5;
    int lane = threadIdx.x & 31;
    if (wid >= 3 * BATCH) return;
    int g = wid / BATCH, b = wid - g * BATCH;
    const float* src;
    if (g == 0)      src = uemb + (size_t)users[b] * EMB;
    else if (g == 1) src = iemb + (size_t)pos[b]   * EMB;
    else             src = iemb + (size_t)neg[b]   * EMB;
    float2 v = *reinterpret_cast<const float2*>(src + 2 * lane);
    *reinterpret_cast<float2*>(out + (size_t)wid * 256 + 2 * lane) = v;
}

// ---------------- 4) SpMM: 4 rows/warp, contiguous nnz stream --------------
// Half-warp per nnz; lane owns a dim quad (LDG.64). Triple-buffered stage,
// prefetch distance 2. Mixed-precision HFMA (fp16 in, fp32 accumulate).
__device__ __forceinline__ void fma_quad_h(float4& acc, unsigned vh2, uint2 raw) {
    unsigned short vh = (unsigned short)vh2;
    __half2 x0 = *reinterpret_cast<__half2*>(&raw.x);
    __half2 x1 = *reinterpret_cast<__half2*>(&raw.y);
    unsigned short h00 = __half_as_ushort(__low2half(x0));
    unsigned short h01 = __half_as_ushort(__high2half(x0));
    unsigned short h10 = __half_as_ushort(__low2half(x1));
    unsigned short h11 = __half_as_ushort(__high2half(x1));
    asm("fma.rn.f32.f16 %0, %1, %2, %0;" : "+f"(acc.x) : "h"(h00), "h"(vh));
    asm("fma.rn.f32.f16 %0, %1, %2, %0;" : "+f"(acc.y) : "h"(h01), "h"(vh));
    asm("fma.rn.f32.f16 %0, %1, %2, %0;" : "+f"(acc.z) : "h"(h10), "h"(vh));
    asm("fma.rn.f32.f16 %0, %1, %2, %0;" : "+f"(acc.w) : "h"(h11), "h"(vh));
}

__device__ __forceinline__ void flush_row(int r, float4& acc, int h, int q,
                                          const char* egoB) {
    acc.x += __shfl_xor_sync(0xffffffffu, acc.x, 16);
    acc.y += __shfl_xor_sync(0xffffffffu, acc.y, 16);
    acc.z += __shfl_xor_sync(0xffffffffu, acc.z, 16);
    acc.w += __shfl_xor_sync(0xffffffffu, acc.w, 16);
    if (h == 0) {                               // side (fp16)
        half2 h0 = __floats2half2_rn(acc.x, acc.y);
        half2 h1 = __floats2half2_rn(acc.z, acc.w);
        uint2 pk;
        pk.x = *reinterpret_cast<unsigned*>(&h0);
        pk.y = *reinterpret_cast<unsigned*>(&h1);
        *reinterpret_cast<uint2*>(g_sideh + (size_t)r * EMB + 4 * q) = pk;
    } else {                                    // prod = ego * side (fp16)
        uint2 raw = *reinterpret_cast<const uint2*>(egoB + ((size_t)r * EMB + 4 * q) * 2);
        float2 f0 = __half22float2(*reinterpret_cast<half2*>(&raw.x));
        float2 f1 = __half22float2(*reinterpret_cast<half2*>(&raw.y));
        half2 h0 = __floats2half2_rn(f0.x * acc.x, f0.y * acc.y);
        half2 h1 = __floats2half2_rn(f1.x * acc.z, f1.y * acc.w);
        uint2 pk;
        pk.x = *reinterpret_cast<unsigned*>(&h0);
        pk.y = *reinterpret_cast<unsigned*>(&h1);
        *reinterpret_cast<uint2*>(g_prodh + (size_t)r * EMB + 4 * q) = pk;
    }
    acc = make_float4(0.f, 0.f, 0.f, 0.f);
}

__global__ void __launch_bounds__(256) spmm_kernel(
        const int* __restrict__ col, const float* __restrict__ val, int src) {
    __shared__ uint2 stage[8][3][32];          // 6 KB: triple-buffered batches
    const char* __restrict__ egoB = (const char*)g_egoh[src];
    int w = threadIdx.x >> 5, lane = threadIdx.x & 31;
    int h = lane >> 4, q = lane & 15;          // half index, dim quad
    const char* laneB = egoB + 8 * q;
    int r0 = (blockIdx.x * 8 + w) * 4;

    // one rowptr fetch for 4 rows (5 ints via lanes + shfl)
    int rp = g_rowptr[r0 + min(lane, 4)];
    int beg = __shfl_sync(0xffffffffu, rp, 0);
    int rend[4];
    rend[0] = __shfl_sync(0xffffffffu, rp, 1) - beg;
    rend[1] = __shfl_sync(0xffffffffu, rp, 2) - beg;
    rend[2] = __shfl_sync(0xffffffffu, rp, 3) - beg;
    rend[3] = __shfl_sync(0xffffffffu, rp, 4) - beg;
    int total = rend[3];

    // preload batches 0 and 1
    #pragma unroll
    for (int k = 0; k < 2; k++) {
        int i = beg + k * 32 + lane;
        if (k * 32 + lane < total) {
            float v = val[i];
            half2 hv = __floats2half2_rn(v, v);
            stage[w][k][lane] = make_uint2(*reinterpret_cast<unsigned*>(&hv),
                                           (unsigned)(col[i] << 7));
        }
    }
    __syncwarp();

    float4 acc = make_float4(0.f, 0.f, 0.f, 0.f);
    int row = 0;
    int slot = 0;
    for (int bs = 0; bs < total; bs += 32) {
        // prefetch batch bs+64 into slot (slot+2)%3
        int pi = bs + 64 + lane;
        if (pi < total) {
            float v = val[beg + pi];
            half2 hv = __floats2half2_rn(v, v);
            int ps = slot + 2; if (ps >= 3) ps -= 3;
            stage[w][ps][lane] = make_uint2(*reinterpret_cast<unsigned*>(&hv),
                                            (unsigned)(col[beg + pi] << 7));
        }
        int cnt = min(32, total - bs);
        const uint2* sb = stage[w][slot];
        int j = 0;
        while (true) {
            // flush rows whose end falls at current position
            while (row < 4 && rend[row] <= bs + j)
                flush_row(r0 + row, acc, h, q, egoB), row++;
            if (j >= cnt) break;
            int segEnd = min(cnt, rend[row] - bs);
            for (; j + 16 <= segEnd; j += 16) {    // 16 nnz, 8 LDG.64/half
                uint2 raw[8]; unsigned v[8];
                #pragma unroll
                for (int t = 0; t < 8; t++) {
                    uint2 cv = sb[j + 2 * t + h];
                    v[t] = cv.x;
                    raw[t] = *reinterpret_cast<const uint2*>(laneB + cv.y);
                }
                #pragma unroll
                for (int t = 0; t < 8; t++) fma_quad_h(acc, v[t], raw[t]);
            }
            for (; j + 2 <= segEnd; j += 2) {
                uint2 cv = sb[j + h];
                uint2 raw = *reinterpret_cast<const uint2*>(laneB + cv.y);
                fma_quad_h(acc, cv.x, raw);
            }
            if (j < segEnd) {
                if (h == 0) {
                    uint2 cv = sb[j];
                    uint2 raw = *reinterpret_cast<const uint2*>(laneB + cv.y);
                    fma_quad_h(acc, cv.x, raw);
                }
                j = segEnd;
            }
        }
        __syncwarp();
        slot++; if (slot >= 3) slot -= 3;
    }
    // flush remaining rows (covers empty trailing rows and total==0)
    while (row < 4)
        flush_row(r0 + row, acc, h, q, egoB), row++;
}

// ---------------- 5) dense via HMMA: ego = leaky([side|prod]@Wcat + bias) --
__device__ __forceinline__ void ldsm_x4(unsigned& r0, unsigned& r1, unsigned& r2, unsigned& r3,
                                        unsigned addr) {
    asm volatile("ldmatrix.sync.aligned.m8n8.x4.shared.b16 {%0,%1,%2,%3}, [%4];"
                 : "=r"(r0), "=r"(r1), "=r"(r2), "=r"(r3) : "r"(addr));
}
__device__ __forceinline__ void ldsm_x4t(unsigned& r0, unsigned& r1, unsigned& r2, unsigned& r3,
                                         unsigned addr) {
    asm volatile("ldmatrix.sync.aligned.m8n8.x4.trans.shared.b16 {%0,%1,%2,%3}, [%4];"
                 : "=r"(r0), "=r"(r1), "=r"(r2), "=r"(r3) : "r"(addr));
}
__device__ __forceinline__ void mma16816(float* c, unsigned a0, unsigned a1, unsigned a2,
                                         unsigned a3, unsigned b0, unsigned b1) {
    asm volatile("mma.sync.aligned.m16n8k16.row.col.f32.f16.f16.f32 "
                 "{%0,%1,%2,%3},{%4,%5,%6,%7},{%8,%9},{%0,%1,%2,%3};"
                 : "+f"(c[0]), "+f"(c[1]), "+f"(c[2]), "+f"(c[3])
                 : "r"(a0), "r"(a1), "r"(a2), "r"(a3), "r"(b0), "r"(b1));
}

// Block: 128 rows, 256 threads (8 warps). Warp w owns m-tile rows [16w,16w+16).
__global__ void __launch_bounds__(256) dense_kernel(int layer, int dst) {
    __shared__ __align__(16) char sA[128 * 256];   // 32 KB
    __shared__ __align__(16) char sB[128 * 128];   // 16 KB
    __half* __restrict__ egoh_next = g_egoh[dst];
    int tid = threadIdx.x, w = tid >> 5, lane = tid & 31;
    int rowbase = blockIdx.x * 128;

    {
        const uint4* gs = reinterpret_cast<const uint4*>(g_sideh + (size_t)rowbase * EMB);
        const uint4* gp = reinterpret_cast<const uint4*>(g_prodh + (size_t)rowbase * EMB);
        #pragma unroll
        for (int i = 0; i < 4; i++) {
            int id = tid + i * 256;               // 1024 chunks each
            int row = id >> 3, c = id & 7;
            bool ok = rowbase + row < N_NODES;
            uint4 vs = ok ? gs[id] : make_uint4(0, 0, 0, 0);
            uint4 vp = ok ? gp[id] : make_uint4(0, 0, 0, 0);
            *reinterpret_cast<uint4*>(sA + row * 256 + ((c       ^ (row & 7)) << 4)) = vs;
            *reinterpret_cast<uint4*>(sA + row * 256 + (((8 + c) ^ (row & 7)) << 4)) = vp;
        }
        const uint4* gw = reinterpret_cast<const uint4*>(g_wh[layer]);
        #pragma unroll
        for (int i = 0; i < 4; i++) {
            int id = tid + i * 256;               // 1024 chunks
            int row = id >> 3, c = id & 7;
            *reinterpret_cast<uint4*>(sB + row * 128 + ((c ^ (row & 7)) << 4)) = gw[id];
        }
    }
    __syncthreads();

    unsigned aBase = (unsigned)__cvta_generic_to_shared(sA);
    unsigned bBase = (unsigned)__cvta_generic_to_shared(sB);

    float acc[8][4];
    #pragma unroll
    for (int j = 0; j < 8; j++)
        #pragma unroll
        for (int t = 0; t < 4; t++) acc[j][t] = 0.f;

    int aRow = w * 16 + (lane & 15);
    int bRowLocal = (lane & 7) + ((lane >> 3) & 1) * 8;

    #pragma unroll
    for (int kt = 0; kt < 8; kt++) {
        unsigned a0, a1, a2, a3;
        {
            int c = 2 * kt + (lane >> 4);
            ldsm_x4(a0, a1, a2, a3, aBase + aRow * 256 + ((c ^ (lane & 7)) << 4));
        }
        unsigned b[8][2];
        #pragma unroll
        for (int g = 0; g < 4; g++) {
            int row = 16 * kt + bRowLocal;
            int c = 2 * g + (lane >> 4);
            ldsm_x4t(b[2 * g][0], b[2 * g][1], b[2 * g + 1][0], b[2 * g + 1][1],
                     bBase + row * 128 + ((c ^ (lane & 7)) << 4));
        }
        #pragma unroll
        for (int j = 0; j < 8; j++)
            mma16816(acc[j], a0, a1, a2, a3, b[j][0], b[j][1]);
    }

    int r0 = rowbase + w * 16 + (lane >> 2);
    int r1 = r0 + 8;
    int cbase = 2 * (lane & 3);
    const float* bias = g_bias[layer];
    #pragma unroll
    for (int j = 0; j < 8; j++) {
        int colv = 8 * j + cbase;
        float2 bj = *reinterpret_cast<const float2*>(bias + colv);
        float x0 = acc[j][0] + bj.x, y0 = acc[j][1] + bj.y;
        float x1 = acc[j][2] + bj.x, y1 = acc[j][3] + bj.y;
        x0 = x0 > 0.f ? x0 : 0.2f * x0;  y0 = y0 > 0.f ? y0 : 0.2f * y0;
        x1 = x1 > 0.f ? x1 : 0.2f * x1;  y1 = y1 > 0.f ? y1 : 0.2f * y1;
        if (r0 < N_NODES)
            *reinterpret_cast<half2*>(egoh_next + (size_t)r0 * EMB + colv)
                = __floats2half2_rn(x0, y0);
        if (r1 < N_NODES)
            *reinterpret_cast<half2*>(egoh_next + (size_t)r1 * EMB + colv)
                = __floats2half2_rn(x1, y1);
    }
}

// ---------------- 6) per-layer gather + l2norm straight into d_out ---------
__global__ void gather_norm(const int* __restrict__ users, const int* __restrict__ pos,
                            const int* __restrict__ neg, int src, float* __restrict__ out,
                            int slice) {
    const __half* __restrict__ ego = g_egoh[src];
    int wid  = (blockIdx.x * blockDim.x + threadIdx.x) >> 5;
    int lane = threadIdx.x & 31;
    if (wid >= 3 * BATCH) return;
    int g = wid / BATCH, b = wid - g * BATCH;
    int node;
    if (g == 0)      node = users[b];
    else if (g == 1) node = N_USER + pos[b];
    else             node = N_USER + neg[b];
    half2 hv = *reinterpret_cast<const half2*>(ego + (size_t)node * EMB + 2 * lane);
    float2 v = __half22float2(hv);
    float ss = v.x * v.x + v.y * v.y;
    #pragma unroll
    for (int o = 16; o; o >>= 1) ss += __shfl_xor_sync(0xffffffffu, ss, o);
    float n = sqrtf(ss);
    float inv = 1.f / fmaxf(n, 1e-12f);
    *reinterpret_cast<float2*>(out + (size_t)wid * 256 + slice * EMB + 2 * lane)
        = make_float2(v.x * inv, v.y * inv);
}

// ---------------- launch ---------------------------------------------------
extern "C" void kernel_launch(void* const* d_in, const int* in_sizes, int n_in,
                              void* d_out, int out_size) {
    const int*   users = (const int*)  d_in[0];
    const int*   pos   = (const int*)  d_in[1];
    const int*   neg   = (const int*)  d_in[2];
    const int*   arow  = (const int*)  d_in[3];
    const int*   acol  = (const int*)  d_in[4];
    const float* aval  = (const float*)d_in[5];
    const float* uemb  = (const float*)d_in[6];
    const float* iemb  = (const float*)d_in[7];
    float* out = (float*)d_out;

    build_rowptr<<<(N_NODES + 256) / 256, 256>>>(arow);
    conv_ego0<<<(N_NODES * EMB / 4 + 255) / 256, 256>>>(
        (const float4*)uemb, (const float4*)iemb);
    conv_weights<<<(3 * 128 * EMB + 3 * EMB + 255) / 256, 256>>>(
        (const float*)d_in[8],  (const float*)d_in[10], (const float*)d_in[9],  (const float*)d_in[11],
        (const float*)d_in[12], (const float*)d_in[14], (const float*)d_in[13], (const float*)d_in[15],
        (const float*)d_in[16], (const float*)d_in[18], (const float*)d_in[17], (const float*)d_in[19]);
    init_out<<<(3 * BATCH * 32) / 256, 256>>>(users, pos, neg, uemb, iemb, out);

    const int SBLK = N_NODES / 32;            // 4 rows/warp, 8 warps/block
    const int DBLK = (N_NODES + 127) / 128;

    // layer 0: egoh[0] -> egoh[1]
    spmm_kernel<<<SBLK, 256>>>(acol, aval, 0);
    dense_kernel<<<DBLK, 256>>>(0, 1);
    gather_norm<<<(3 * BATCH * 32) / 256, 256>>>(users, pos, neg, 1, out, 1);

    // layer 1: egoh[1] -> egoh[0]
    spmm_kernel<<<SBLK, 256>>>(acol, aval, 1);
    dense_kernel<<<DBLK, 256>>>(1, 0);
    gather_norm<<<(3 * BATCH * 32) / 256, 256>>>(users, pos, neg, 0, out, 2);

    // layer 2: egoh[0] -> egoh[1]
    spmm_kernel<<<SBLK, 256>>>(acol, aval, 0);
    dense_kernel<<<DBLK, 256>>>(2, 1);
    gather_norm<<<(3 * BATCH * 32) / 256, 256>>>(users, pos, neg, 1, out, 3);
}

// round 17
// speedup vs baseline: 1.1912x; 1.1912x over previous
#include <cuda_runtime.h>
#include <cuda_fp16.h>

#define N_USER 100000
#define N_NODES 200000
#define NNZ 6400000
#define EMB 64
#define BATCH 1024

// ---------------- scratch (device globals; no allocation allowed) ----------
__device__ int    g_rowptr[N_NODES + 1];
__device__ __half g_egoh[2][(size_t)N_NODES * EMB];   // fp16 ego ping-pong
__device__ __half g_sideh[(size_t)N_NODES * EMB];
__device__ __half g_prodh[(size_t)N_NODES * EMB];
__device__ __half g_wh[3][128 * EMB];                 // [Wgc;Wbi] fp16, row-major (k,n)
__device__ float  g_bias[3][EMB];                     // bgc + bbi

// ---------------- 0) fused prologue: 4 independent jobs, one launch --------
// blocks [0, B_RP)                : rowptr binary search
// blocks [B_RP, B_RP+B_EGO)      : fp16 ego0 convert
// blocks [.., +B_W)              : fp16 weights + fused bias
// blocks [.., +B_OUT)            : output slice 0 gather
#define B_RP   ((N_NODES + 1 + 255) / 256)                  // 782
#define B_EGO  ((N_NODES * EMB / 4 + 255) / 256)            // 3125
#define B_W    ((3 * 128 * EMB + 3 * EMB + 255) / 256)      // 97
#define B_OUT  ((3 * BATCH * 32) / 256)                     // 384
#define B_TOT  (B_RP + B_EGO + B_W + B_OUT)

__global__ void __launch_bounds__(256) prologue(
        const int* __restrict__ row,
        const float4* __restrict__ uemb4, const float4* __restrict__ iemb4,
        const float* __restrict__ uemb,  const float* __restrict__ iemb,
        const int* __restrict__ users, const int* __restrict__ pos,
        const int* __restrict__ neg, float* __restrict__ out,
        const float* Wg0, const float* Wb0, const float* bg0, const float* bb0,
        const float* Wg1, const float* Wb1, const float* bg1, const float* bb1,
        const float* Wg2, const float* Wb2, const float* bg2, const float* bb2) {
    int blk = blockIdx.x;
    if (blk < B_RP) {
        int r = blk * 256 + threadIdx.x;
        if (r > N_NODES) return;
        int lo = 0, hi = NNZ;
        while (lo < hi) {
            int mid = (lo + hi) >> 1;
            if (row[mid] < r) lo = mid + 1; else hi = mid;
        }
        g_rowptr[r] = lo;
        return;
    }
    blk -= B_RP;
    if (blk < B_EGO) {
        int i = blk * 256 + threadIdx.x;
        const int NU4 = N_USER * EMB / 4;
        const int NT4 = N_NODES * EMB / 4;
        if (i >= NT4) return;
        float4 v = (i < NU4) ? uemb4[i] : iemb4[i - NU4];
        half2 h0 = __floats2half2_rn(v.x, v.y);
        half2 h1 = __floats2half2_rn(v.z, v.w);
        uint2 pk;
        pk.x = *reinterpret_cast<unsigned*>(&h0);
        pk.y = *reinterpret_cast<unsigned*>(&h1);
        reinterpret_cast<uint2*>(g_egoh[0])[i] = pk;
        return;
    }
    blk -= B_EGO;
    if (blk < B_W) {
        const float* Wg[3] = {Wg0, Wg1, Wg2};
        const float* Wb[3] = {Wb0, Wb1, Wb2};
        const float* bg[3] = {bg0, bg1, bg2};
        const float* bb[3] = {bb0, bb1, bb2};
        int i = blk * 256 + threadIdx.x;
        if (i < 3 * 128 * EMB) {
            int l = i / (128 * EMB), rem = i % (128 * EMB);
            int k = rem / EMB, n = rem % EMB;
            float w = (k < EMB) ? Wg[l][k * EMB + n] : Wb[l][(k - EMB) * EMB + n];
            g_wh[l][rem] = __float2half_rn(w);
        } else if (i < 3 * 128 * EMB + 3 * EMB) {
            int j = i - 3 * 128 * EMB;
            int l = j / EMB, n = j % EMB;
            g_bias[l][n] = bg[l][n] + bb[l][n];
        }
        return;
    }
    blk -= B_W;
    {
        int wid  = (blk * 256 + threadIdx.x) >> 5;
        int lane = threadIdx.x & 31;
        if (wid >= 3 * BATCH) return;
        int g = wid / BATCH, b = wid - g * BATCH;
        const float* src;
        if (g == 0)      src = uemb + (size_t)users[b] * EMB;
        else if (g == 1) src = iemb + (size_t)pos[b]   * EMB;
        else             src = iemb + (size_t)neg[b]   * EMB;
        float2 v = *reinterpret_cast<const float2*>(src + 2 * lane);
        *reinterpret_cast<float2*>(out + (size_t)wid * 256 + 2 * lane) = v;
    }
}

// ---------------- 4) SpMM over fp16 ego; fp16 side/prod out ----------------
// Warp per row. Half-warp per nnz; lane owns a dim quad (LDG.64).
// Double-buffered (val,col) staging + mixed-precision HFMA accumulate.
__device__ __forceinline__ void fma_quad_h(float4& acc, unsigned vh2, uint2 raw) {
    unsigned short vh = (unsigned short)vh2;
    __half2 x0 = *reinterpret_cast<__half2*>(&raw.x);
    __half2 x1 = *reinterpret_cast<__half2*>(&raw.y);
    unsigned short h00 = __half_as_ushort(__low2half(x0));
    unsigned short h01 = __half_as_ushort(__high2half(x0));
    unsigned short h10 = __half_as_ushort(__low2half(x1));
    unsigned short h11 = __half_as_ushort(__high2half(x1));
    asm("fma.rn.f32.f16 %0, %1, %2, %0;" : "+f"(acc.x) : "h"(h00), "h"(vh));
    asm("fma.rn.f32.f16 %0, %1, %2, %0;" : "+f"(acc.y) : "h"(h01), "h"(vh));
    asm("fma.rn.f32.f16 %0, %1, %2, %0;" : "+f"(acc.z) : "h"(h10), "h"(vh));
    asm("fma.rn.f32.f16 %0, %1, %2, %0;" : "+f"(acc.w) : "h"(h11), "h"(vh));
}

__global__ void __launch_bounds__(256) spmm_kernel(
        const int* __restrict__ col, const float* __restrict__ val, int src) {
    __shared__ uint2 stage[8][2][32];          // 4 KB: double-buffered batches
    const char* __restrict__ egoB = (const char*)g_egoh[src];
    int w = threadIdx.x >> 5, lane = threadIdx.x & 31;
    int h = lane >> 4, q = lane & 15;          // half index, dim quad
    const char* laneB = egoB + 8 * q;
    int r = blockIdx.x * 8 + w;
    int beg = g_rowptr[r], end = g_rowptr[r + 1];
    float4 acc = make_float4(0.f, 0.f, 0.f, 0.f);

    // preload batch 0
    {
        int i = beg + lane;
        if (i < end) {
            float v = val[i];
            half2 hv = __floats2half2_rn(v, v);
            stage[w][0][lane] = make_uint2(*reinterpret_cast<unsigned*>(&hv),
                                           (unsigned)(col[i] << 7));
        }
    }
    __syncwarp();

    int buf = 0;
    for (int bs = beg; bs < end; bs += 32) {
        // prefetch next batch into the other buffer (no sync needed: disjoint)
        int ni = bs + 32 + lane;
        if (ni < end) {
            float v = val[ni];
            half2 hv = __floats2half2_rn(v, v);
            stage[w][buf ^ 1][lane] = make_uint2(*reinterpret_cast<unsigned*>(&hv),
                                                  (unsigned)(col[ni] << 7));
        }
        int cnt = min(32, end - bs);
        int j = 0;
        for (; j + 16 <= cnt; j += 16) {       // 16 nnz, 8 LDG.64 in flight/half
            uint2 raw[8]; unsigned v[8];
            #pragma unroll
            for (int t = 0; t < 8; t++) {
                uint2 cv = stage[w][buf][j + 2 * t + h];
                v[t] = cv.x;
                raw[t] = *reinterpret_cast<const uint2*>(laneB + cv.y);
            }
            #pragma unroll
            for (int t = 0; t < 8; t++) fma_quad_h(acc, v[t], raw[t]);
        }
        for (; j + 2 <= cnt; j += 2) {
            uint2 cv = stage[w][buf][j + h];
            uint2 raw = *reinterpret_cast<const uint2*>(laneB + cv.y);
            fma_quad_h(acc, cv.x, raw);
        }
        if (j < cnt && h == 0) {
            uint2 cv = stage[w][buf][j];
            uint2 raw = *reinterpret_cast<const uint2*>(laneB + cv.y);
            fma_quad_h(acc, cv.x, raw);
        }
        __syncwarp();                           // prefetch visible; buffer free
        buf ^= 1;
    }
    acc.x += __shfl_xor_sync(0xffffffffu, acc.x, 16);
    acc.y += __shfl_xor_sync(0xffffffffu, acc.y, 16);
    acc.z += __shfl_xor_sync(0xffffffffu, acc.z, 16);
    acc.w += __shfl_xor_sync(0xffffffffu, acc.w, 16);

    if (h == 0) {                               // side (fp16)
        half2 h0 = __floats2half2_rn(acc.x, acc.y);
        half2 h1 = __floats2half2_rn(acc.z, acc.w);
        uint2 pk;
        pk.x = *reinterpret_cast<unsigned*>(&h0);
        pk.y = *reinterpret_cast<unsigned*>(&h1);
        *reinterpret_cast<uint2*>(g_sideh + (size_t)r * EMB + 4 * q) = pk;
    } else {                                    // prod = ego * side (fp16)
        uint2 raw = *reinterpret_cast<const uint2*>(egoB + ((size_t)r * EMB + 4 * q) * 2);
        float2 f0 = __half22float2(*reinterpret_cast<half2*>(&raw.x));
        float2 f1 = __half22float2(*reinterpret_cast<half2*>(&raw.y));
        half2 h0 = __floats2half2_rn(f0.x * acc.x, f0.y * acc.y);
        half2 h1 = __floats2half2_rn(f1.x * acc.z, f1.y * acc.w);
        uint2 pk;
        pk.x = *reinterpret_cast<unsigned*>(&h0);
        pk.y = *reinterpret_cast<unsigned*>(&h1);
        *reinterpret_cast<uint2*>(g_prodh + (size_t)r * EMB + 4 * q) = pk;
    }
}

// ---------------- 5) dense via HMMA: ego = leaky([side|prod]@Wcat + bias) --
__device__ __forceinline__ void ldsm_x4(unsigned& r0, unsigned& r1, unsigned& r2, unsigned& r3,
                                        unsigned addr) {
    asm volatile("ldmatrix.sync.aligned.m8n8.x4.shared.b16 {%0,%1,%2,%3}, [%4];"
                 : "=r"(r0), "=r"(r1), "=r"(r2), "=r"(r3) : "r"(addr));
}
__device__ __forceinline__ void ldsm_x4t(unsigned& r0, unsigned& r1, unsigned& r2, unsigned& r3,
                                         unsigned addr) {
    asm volatile("ldmatrix.sync.aligned.m8n8.x4.trans.shared.b16 {%0,%1,%2,%3}, [%4];"
                 : "=r"(r0), "=r"(r1), "=r"(r2), "=r"(r3) : "r"(addr));
}
__device__ __forceinline__ void mma16816(float* c, unsigned a0, unsigned a1, unsigned a2,
                                         unsigned a3, unsigned b0, unsigned b1) {
    asm volatile("mma.sync.aligned.m16n8k16.row.col.f32.f16.f16.f32 "
                 "{%0,%1,%2,%3},{%4,%5,%6,%7},{%8,%9},{%0,%1,%2,%3};"
                 : "+f"(c[0]), "+f"(c[1]), "+f"(c[2]), "+f"(c[3])
                 : "r"(a0), "r"(a1), "r"(a2), "r"(a3), "r"(b0), "r"(b1));
}

// Block: 128 rows, 256 threads (8 warps). Warp w owns m-tile rows [16w,16w+16).
__global__ void __launch_bounds__(256) dense_kernel(int layer, int dst) {
    __shared__ __align__(16) char sA[128 * 256];   // 32 KB
    __shared__ __align__(16) char sB[128 * 128];   // 16 KB
    __half* __restrict__ egoh_next = g_egoh[dst];
    int tid = threadIdx.x, w = tid >> 5, lane = tid & 31;
    int rowbase = blockIdx.x * 128;

    {
        const uint4* gs = reinterpret_cast<const uint4*>(g_sideh + (size_t)rowbase * EMB);
        const uint4* gp = reinterpret_cast<const uint4*>(g_prodh + (size_t)rowbase * EMB);
        #pragma unroll
        for (int i = 0; i < 4; i++) {
            int id = tid + i * 256;               // 1024 chunks each
            int row = id >> 3, c = id & 7;
            bool ok = rowbase + row < N_NODES;
            uint4 vs = ok ? gs[id] : make_uint4(0, 0, 0, 0);
            uint4 vp = ok ? gp[id] : make_uint4(0, 0, 0, 0);
            *reinterpret_cast<uint4*>(sA + row * 256 + ((c       ^ (row & 7)) << 4)) = vs;
            *reinterpret_cast<uint4*>(sA + row * 256 + (((8 + c) ^ (row & 7)) << 4)) = vp;
        }
        const uint4* gw = reinterpret_cast<const uint4*>(g_wh[layer]);
        #pragma unroll
        for (int i = 0; i < 4; i++) {
            int id = tid + i * 256;               // 1024 chunks
            int row = id >> 3, c = id & 7;
            *reinterpret_cast<uint4*>(sB + row * 128 + ((c ^ (row & 7)) << 4)) = gw[id];
        }
    }
    __syncthreads();

    unsigned aBase = (unsigned)__cvta_generic_to_shared(sA);
    unsigned bBase = (unsigned)__cvta_generic_to_shared(sB);

    float acc[8][4];
    #pragma unroll
    for (int j = 0; j < 8; j++)
        #pragma unroll
        for (int t = 0; t < 4; t++) acc[j][t] = 0.f;

    int aRow = w * 16 + (lane & 15);
    int bRowLocal = (lane & 7) + ((lane >> 3) & 1) * 8;

    #pragma unroll
    for (int kt = 0; kt < 8; kt++) {
        unsigned a0, a1, a2, a3;
        {
            int c = 2 * kt + (lane >> 4);
            ldsm_x4(a0, a1, a2, a3, aBase + aRow * 256 + ((c ^ (lane & 7)) << 4));
        }
        unsigned b[8][2];
        #pragma unroll
        for (int g = 0; g < 4; g++) {
            int row = 16 * kt + bRowLocal;
            int c = 2 * g + (lane >> 4);
            ldsm_x4t(b[2 * g][0], b[2 * g][1], b[2 * g + 1][0], b[2 * g + 1][1],
                     bBase + row * 128 + ((c ^ (lane & 7)) << 4));
        }
        #pragma unroll
        for (int j = 0; j < 8; j++)
            mma16816(acc[j], a0, a1, a2, a3, b[j][0], b[j][1]);
    }

    int r0 = rowbase + w * 16 + (lane >> 2);
    int r1 = r0 + 8;
    int cbase = 2 * (lane & 3);
    const float* bias = g_bias[layer];
    #pragma unroll
    for (int j = 0; j < 8; j++) {
        int colv = 8 * j + cbase;
        float2 bj = *reinterpret_cast<const float2*>(bias + colv);
        float x0 = acc[j][0] + bj.x, y0 = acc[j][1] + bj.y;
        float x1 = acc[j][2] + bj.x, y1 = acc[j][3] + bj.y;
        x0 = x0 > 0.f ? x0 : 0.2f * x0;  y0 = y0 > 0.f ? y0 : 0.2f * y0;
        x1 = x1 > 0.f ? x1 : 0.2f * x1;  y1 = y1 > 0.f ? y1 : 0.2f * y1;
        if (r0 < N_NODES)
            *reinterpret_cast<half2*>(egoh_next + (size_t)r0 * EMB + colv)
                = __floats2half2_rn(x0, y0);
        if (r1 < N_NODES)
            *reinterpret_cast<half2*>(egoh_next + (size_t)r1 * EMB + colv)
                = __floats2half2_rn(x1, y1);
    }
}

// ---------------- 6) per-layer gather + l2norm straight into d_out ---------
__global__ void gather_norm(const int* __restrict__ users, const int* __restrict__ pos,
                            const int* __restrict__ neg, int src, float* __restrict__ out,
                            int slice) {
    const __half* __restrict__ ego = g_egoh[src];
    int wid  = (blockIdx.x * blockDim.x + threadIdx.x) >> 5;
    int lane = threadIdx.x & 31;
    if (wid >= 3 * BATCH) return;
    int g = wid / BATCH, b = wid - g * BATCH;
    int node;
    if (g == 0)      node = users[b];
    else if (g == 1) node = N_USER + pos[b];
    else             node = N_USER + neg[b];
    half2 hv = *reinterpret_cast<const half2*>(ego + (size_t)node * EMB + 2 * lane);
    float2 v = __half22float2(hv);
    float ss = v.x * v.x + v.y * v.y;
    #pragma unroll
    for (int o = 16; o; o >>= 1) ss += __shfl_xor_sync(0xffffffffu, ss, o);
    float n = sqrtf(ss);
    float inv = 1.f / fmaxf(n, 1e-12f);
    *reinterpret_cast<float2*>(out + (size_t)wid * 256 + slice * EMB + 2 * lane)
        = make_float2(v.x * inv, v.y * inv);
}

// ---------------- launch ---------------------------------------------------
extern "C" void kernel_launch(void* const* d_in, const int* in_sizes, int n_in,
                              void* d_out, int out_size) {
    const int*   users = (const int*)  d_in[0];
    const int*   pos   = (const int*)  d_in[1];
    const int*   neg   = (const int*)  d_in[2];
    const int*   arow  = (const int*)  d_in[3];
    const int*   acol  = (const int*)  d_in[4];
    const float* aval  = (const float*)d_in[5];
    const float* uemb  = (const float*)d_in[6];
    const float* iemb  = (const float*)d_in[7];
    float* out = (float*)d_out;

    prologue<<<B_TOT, 256>>>(
        arow, (const float4*)uemb, (const float4*)iemb, uemb, iemb,
        users, pos, neg, out,
        (const float*)d_in[8],  (const float*)d_in[10], (const float*)d_in[9],  (const float*)d_in[11],
        (const float*)d_in[12], (const float*)d_in[14], (const float*)d_in[13], (const float*)d_in[15],
        (const float*)d_in[16], (const float*)d_in[18], (const float*)d_in[17], (const float*)d_in[19]);

    const int SBLK = N_NODES / 8;
    const int DBLK = (N_NODES + 127) / 128;

    // layer 0: egoh[0] -> egoh[1]
    spmm_kernel<<<SBLK, 256>>>(acol, aval, 0);
    dense_kernel<<<DBLK, 256>>>(0, 1);
    gather_norm<<<(3 * BATCH * 32) / 256, 256>>>(users, pos, neg, 1, out, 1);

    // layer 1: egoh[1] -> egoh[0]
    spmm_kernel<<<SBLK, 256>>>(acol, aval, 1);
    dense_kernel<<<DBLK, 256>>>(1, 0);
    gather_norm<<<(3 * BATCH * 32) / 256, 256>>>(users, pos, neg, 0, out, 2);

    // layer 2: egoh[0] -> egoh[1]
    spmm_kernel<<<SBLK, 256>>>(acol, aval, 0);
    dense_kernel<<<DBLK, 256>>>(2, 1);
    gather_norm<<<(3 * BATCH * 32) / 256, 256>>>(users, pos, neg, 1, out, 3);
}